// round 7
// baseline (speedup 1.0000x reference)
#include <cuda_runtime.h>

// Shapes (fixed by the problem): N=8192 rows, D=128 feat, C=1000 classes.
#define N_MAX 8192
#define D_FIX 128
#define NBINS 1024
#define NCE_INV_T 10.0f
#define EPSV 1e-10f

// ---------------- device scratch (no allocations allowed) ----------------
__device__ float  g_f1[N_MAX * D_FIX];   // normalized fs, pre-scaled by 1/T
__device__ float  g_f2[N_MAX * D_FIX];   // normalized ft
__device__ float  g_S1[N_MAX], g_S2[N_MAX], g_S3[N_MAX]; // row sums of e, e^2, e^3
__device__ int    g_tgt[N_MAX];
__device__ int    g_cnt[NBINS], g_off[NBINS], g_cur[NBINS];
__device__ int    g_sorted[N_MAX];       // row indices grouped by class
__device__ int    g_is64;                // 1 if target buffer is int64
__device__ double g_acc;

// ---------------- K0: zero accumulators (fresh every replay) ----------------
__global__ void k_init() {
    int i = blockIdx.x * blockDim.x + threadIdx.x;
    if (i < N_MAX) { g_S1[i] = 0.f; g_S2[i] = 0.f; g_S3[i] = 0.f; }
    if (i < NBINS) { g_cnt[i] = 0; g_cur[i] = 0; }
    if (i == 0) g_acc = 0.0;
}

// ---------------- K0b: detect target dtype (int64 vs int32) ------------------
// Reads only the first 128 int32 words — in-bounds for either dtype (int32
// buffer has N=8192 words). If the buffer holds little-endian int64 values in
// [0,100), every odd word is the zero high-half. For int32 data the odd words
// are random class ids; all-64-zero has probability ~(1/100)^64 ~= 0.
__global__ void k_detect(const int* __restrict__ w) {
    int nz = 0;
    for (int i = threadIdx.x; i < 64; i += 32)
        if (w[2 * i + 1] != 0) nz = 1;
    #pragma unroll
    for (int o = 16; o; o >>= 1) nz |= __shfl_xor_sync(0xffffffffu, nz, o);
    if (threadIdx.x == 0) g_is64 = nz ? 0 : 1;
}

// ---------------- K1: L2-normalize rows; scale f1 by 1/NCE_T ----------------
__global__ void k_norm(const float* __restrict__ fs, const float* __restrict__ ft, int N) {
    int row = blockIdx.x;
    bool is_s = (row < N);
    int r = is_s ? row : row - N;
    const float* src = is_s ? fs : ft;
    float* dst = is_s ? g_f1 : g_f2;
    float v = src[r * D_FIX + threadIdx.x];
    float ss = v * v;
    #pragma unroll
    for (int o = 16; o; o >>= 1) ss += __shfl_xor_sync(0xffffffffu, ss, o);
    __shared__ float ws[4];
    if ((threadIdx.x & 31) == 0) ws[threadIdx.x >> 5] = ss;
    __syncthreads();
    float tot = ws[0] + ws[1] + ws[2] + ws[3];
    float nrm = fmaxf(sqrtf(tot), 1e-12f);
    float scale = (is_s ? NCE_INV_T : 1.0f) / nrm;
    dst[r * D_FIX + threadIdx.x] = v * scale;
}

// ---------------- K2: class histogram + dtype-aware load ----------------
__global__ void k_count(const int* __restrict__ w, int N) {
    int i = blockIdx.x * blockDim.x + threadIdx.x;
    if (i < N) {
        int c = g_is64 ? w[2 * i] : w[i];
        if (c < 0 || c >= NBINS) c = 0;   // safety clamp (should never trigger)
        g_tgt[i] = c;
        atomicAdd(&g_cnt[c], 1);
    }
}

// ---------------- K3: exclusive scan over class counts (1 block) -------------
__global__ void k_scan() {
    __shared__ int s[NBINS];
    int t = threadIdx.x;
    s[t] = g_cnt[t];
    __syncthreads();
    for (int off = 1; off < NBINS; off <<= 1) {
        int v = (t >= off) ? s[t - off] : 0;
        __syncthreads();
        s[t] += v;
        __syncthreads();
    }
    g_off[t] = s[t] - g_cnt[t];
}

// ---------------- K4: scatter row ids grouped by class ----------------
__global__ void k_scatter(int N) {
    int i = blockIdx.x * blockDim.x + threadIdx.x;
    if (i < N) {
        int c = g_tgt[i];
        int p = atomicAdd(&g_cur[c], 1);
        g_sorted[g_off[c] + p] = i;
    }
}

// ---------------- K5: fused GEMM (f32x2 packed FMA) + exp + row power sums ----
// C[i,j] = <f1[i], f2[j]> = 10*cos; per row accumulate S1=sum e, S2=sum e^2,
// S3=sum e^3 with e = exp(C). No max-subtraction needed (C <= 10).
// Tile: 128x128 per CTA, 256 threads, 8x8 per thread (8 rows x 4 f32x2 pairs).
__global__ __launch_bounds__(256, 2) void k_gemm() {
    __shared__ __align__(16) float sbuf[32 * 129 + 32 * 132];
    #define SA(k, m) sbuf[(k) * 129 + (m)]
    #define SB(k, m) sbuf[32 * 129 + (k) * 132 + (m)]
    int tid = threadIdx.x;
    int tx = tid & 15, ty = tid >> 4;
    int row0 = blockIdx.y << 7, col0 = blockIdx.x << 7;

    unsigned long long acc2[8][4];
    #pragma unroll
    for (int r = 0; r < 8; r++)
        #pragma unroll
        for (int p = 0; p < 4; p++) acc2[r][p] = 0ull;

    for (int kk = 0; kk < D_FIX; kk += 32) {
        #pragma unroll
        for (int i = 0; i < 16; i++) {
            int lin = i * 256 + tid;          // 0..4095
            int k = lin & 31, m = lin >> 5;   // coalesced over k
            SA(k, m) = g_f1[(row0 + m) * D_FIX + kk + k];
            SB(k, m) = g_f2[(col0 + m) * D_FIX + kk + k];
        }
        __syncthreads();
        #pragma unroll
        for (int k = 0; k < 32; k++) {
            unsigned long long a2[8], b2[4];
            #pragma unroll
            for (int r = 0; r < 8; r++) {
                float av = SA(k, ty * 8 + r);                    // broadcast LDS
                asm("mov.b64 %0, {%1, %1};" : "=l"(a2[r]) : "f"(av));
            }
            #pragma unroll
            for (int q = 0; q < 2; q++) {                        // LDS.128
                ulonglong2 bv = *reinterpret_cast<const ulonglong2*>(&SB(k, 4 * tx + 64 * q));
                b2[2 * q] = bv.x; b2[2 * q + 1] = bv.y;
            }
            #pragma unroll
            for (int r = 0; r < 8; r++)
                #pragma unroll
                for (int p = 0; p < 4; p++)
                    asm("fma.rn.f32x2 %0, %1, %2, %0;"
                        : "+l"(acc2[r][p]) : "l"(a2[r]), "l"(b2[p]));
        }
        __syncthreads();
    }

    // epilogue: e = exp(C); per-row partials of e, e^2, e^3
    float p1[8], p2[8], p3[8];
    #pragma unroll
    for (int r = 0; r < 8; r++) {
        p1[r] = p2[r] = p3[r] = 0.f;
        #pragma unroll
        for (int p = 0; p < 4; p++) {
            float v0 = __uint_as_float((unsigned)acc2[r][p]);
            float v1 = __uint_as_float((unsigned)(acc2[r][p] >> 32));
            float e0 = __expf(v0), e1 = __expf(v1);
            p1[r] += e0 + e1;
            float s0 = e0 * e0, s1 = e1 * e1;
            p2[r] += s0 + s1;
            p3[r] += s0 * e0 + s1 * e1;
        }
    }
    // reduce across the 16 tx threads sharing each row, then one atomic per row
    float* red = sbuf;
    __syncthreads();
    #pragma unroll
    for (int r = 0; r < 8; r++) red[(ty * 8 + r) * 16 + tx] = p1[r];
    __syncthreads();
    if (tid < 128) {
        float s = 0.f;
        #pragma unroll
        for (int t = 0; t < 16; t++) s += red[tid * 16 + t];
        atomicAdd(&g_S1[row0 + tid], s);
    }
    __syncthreads();
    #pragma unroll
    for (int r = 0; r < 8; r++) red[(ty * 8 + r) * 16 + tx] = p2[r];
    __syncthreads();
    if (tid < 128) {
        float s = 0.f;
        #pragma unroll
        for (int t = 0; t < 16; t++) s += red[tid * 16 + t];
        atomicAdd(&g_S2[row0 + tid], s);
    }
    __syncthreads();
    #pragma unroll
    for (int r = 0; r < 8; r++) red[(ty * 8 + r) * 16 + tx] = p3[r];
    __syncthreads();
    if (tid < 128) {
        float s = 0.f;
        #pragma unroll
        for (int t = 0; t < 16; t++) s += red[tid * 16 + t];
        atomicAdd(&g_S3[row0 + tid], s);
    }
    #undef SA
    #undef SB
}

// ---------------- K6: exact pos-pair terms + assemble NCE row loss ------------
// For row i: pos set = all j with same class (~82 of them). Recompute those
// logits exactly (tiny), compute sum -log(ps+eps) exactly, and subtract the
// pos contribution from the series-approximated total of -log(1-ps+eps):
//   -log(1-x) = x + x^2/2 + x^3/3 + O(x^4), valid since ps <= ~0.005.
//   Sum over ALL j of the series = 1 + S2/(2 Z^2) + S3/(3 Z^3)  (sum ps = 1).
__global__ void k_pos(int N) {
    int i = blockIdx.x;
    int tid = threadIdx.x; // 128
    int c = g_tgt[i];
    int pcnt = g_cnt[c];
    int base = g_off[c];
    __shared__ __align__(16) float frow[D_FIX];
    frow[tid] = g_f1[i * D_FIX + tid];
    __syncthreads();
    float invZ = 1.0f / g_S1[i];
    float plog = 0.f, pser = 0.f;
    for (int t = tid; t < pcnt; t += 128) {
        int j = g_sorted[base + t];
        const float4* br = reinterpret_cast<const float4*>(g_f2 + j * D_FIX);
        const float4* ar = reinterpret_cast<const float4*>(frow);
        float dot = 0.f;
        #pragma unroll
        for (int q = 0; q < D_FIX / 4; q++) {
            float4 b4 = br[q], a4 = ar[q];
            dot += a4.x * b4.x + a4.y * b4.y + a4.z * b4.z + a4.w * b4.w;
        }
        float ps = __expf(dot) * invZ;
        plog -= __logf(ps + EPSV);
        pser += ps * (1.0f + ps * (0.5f + ps * (1.0f / 3.0f)));
    }
    #pragma unroll
    for (int o = 16; o; o >>= 1) {
        plog += __shfl_xor_sync(0xffffffffu, plog, o);
        pser += __shfl_xor_sync(0xffffffffu, pser, o);
    }
    __shared__ float r1[4], r2[4];
    if ((tid & 31) == 0) { r1[tid >> 5] = plog; r2[tid >> 5] = pser; }
    __syncthreads();
    if (tid == 0) {
        plog = r1[0] + r1[1] + r1[2] + r1[3];
        pser = r2[0] + r2[1] + r2[2] + r2[3];
        float s2 = g_S2[i] * invZ * invZ;
        float s3 = g_S3[i] * invZ * invZ * invZ;
        float tot = 1.0f + 0.5f * s2 + (1.0f / 3.0f) * s3;  // all-j series sum
        float negs = tot - pser;                             // neg-only part
        float row = plog / (float)pcnt + negs / (float)(N - pcnt);
        atomicAdd(&g_acc, (double)row / (double)N);
    }
}

// ---------------- K7: JSD rows (T=1) -----------------------------------------
// 0.5/N * sum_j (pt - ps) * (log pt - log ps), per row, accumulated.
__global__ void k_jsd(const float* __restrict__ ls, const float* __restrict__ lt,
                      int N, int C) {
    int i = blockIdx.x;
    int tid = threadIdx.x; // 256
    const float* s = ls + (size_t)i * C;
    const float* t = lt + (size_t)i * C;
    float es = 0.f, et = 0.f;
    for (int j = tid; j < C; j += 256) { es += __expf(s[j]); et += __expf(t[j]); }
    #pragma unroll
    for (int o = 16; o; o >>= 1) {
        es += __shfl_xor_sync(0xffffffffu, es, o);
        et += __shfl_xor_sync(0xffffffffu, et, o);
    }
    __shared__ float w1[8], w2[8];
    if ((tid & 31) == 0) { w1[tid >> 5] = es; w2[tid >> 5] = et; }
    __syncthreads();
    __shared__ float bs, bt;
    if (tid == 0) {
        float a = 0.f, b = 0.f;
        #pragma unroll
        for (int w = 0; w < 8; w++) { a += w1[w]; b += w2[w]; }
        bs = a; bt = b;
    }
    __syncthreads();
    float lzs = __logf(bs), lzt = __logf(bt);
    float invs = 1.0f / bs, invt = 1.0f / bt;
    float kl = 0.f;
    for (int j = tid; j < C; j += 256) {
        float a = s[j], b = t[j];
        float dl = (b - lzt) - (a - lzs);     // log pt - log ps
        float pt = __expf(b) * invt;
        float ps = __expf(a) * invs;
        kl += (pt - ps) * dl;
    }
    #pragma unroll
    for (int o = 16; o; o >>= 1) kl += __shfl_xor_sync(0xffffffffu, kl, o);
    if ((tid & 31) == 0) w1[tid >> 5] = kl;
    __syncthreads();
    if (tid == 0) {
        float a = 0.f;
        #pragma unroll
        for (int w = 0; w < 8; w++) a += w1[w];
        atomicAdd(&g_acc, 0.5 * (double)a / (double)N);
    }
}

// ---------------- K8: write scalar output ----------------
__global__ void k_final(float* out) {
    if (threadIdx.x == 0) out[0] = (float)g_acc;
}

// ---------------- launcher ----------------
extern "C" void kernel_launch(void* const* d_in, const int* in_sizes, int n_in,
                              void* d_out, int out_size) {
    const float* fs = (const float*)d_in[0];
    const float* ft = (const float*)d_in[1];
    const float* ls = (const float*)d_in[2];
    const float* lt = (const float*)d_in[3];
    const int*   tg = (const int*)d_in[4];   // int32 or int64 words, detected on-device
    int N = in_sizes[4];
    int C = in_sizes[2] / N;

    k_init<<<(N_MAX + 255) / 256, 256>>>();
    k_detect<<<1, 32>>>(tg);
    k_norm<<<2 * N, D_FIX>>>(fs, ft, N);
    k_count<<<(N + 255) / 256, 256>>>(tg, N);
    k_scan<<<1, NBINS>>>();
    k_scatter<<<(N + 255) / 256, 256>>>(N);
    dim3 grid(N / 128, N / 128);
    k_gemm<<<grid, 256>>>();
    k_pos<<<N, 128>>>(N);
    k_jsd<<<N, 256>>>(ls, lt, N, C);
    k_final<<<1, 32>>>((float*)d_out);
}

// round 10
// speedup vs baseline: 3.8283x; 3.8283x over previous
#include <cuda_runtime.h>
#include <cuda_bf16.h>
#include <cstdint>

// Shapes (fixed by the problem): N=8192 rows, D=128 feat, C=1000 classes.
#define N_MAX 8192
#define D_FIX 128
#define NBINS 1024
#define NCE_INV_T 10.0f
#define EPSV 1e-10f

#define TILE 128
#define ROWE 136                     // padded row stride (elements) -> 272 B (16B-aligned, +16B skew)
#define TILE_BYTES (TILE * ROWE * 2) // 34816 B per operand tile
#define SMEM_GEMM (2 * TILE_BYTES)   // 69632 B

// ---------------- device scratch (no allocations allowed) ----------------
__device__ float  g_f1[N_MAX * D_FIX];   // normalized fs * 10 (fp32, for k_pos)
__device__ float  g_f2[N_MAX * D_FIX];   // normalized ft (fp32, for k_pos)
__device__ __align__(16) __nv_bfloat16 g_a16[N_MAX * ROWE]; // bf16 A, padded rows
__device__ __align__(16) __nv_bfloat16 g_b16[N_MAX * ROWE]; // bf16 B, padded rows
__device__ float  g_S1[N_MAX], g_S2[N_MAX], g_S3[N_MAX]; // row sums of e, e^2, e^3
__device__ int    g_tgt[N_MAX];
__device__ int    g_cnt[NBINS], g_off[NBINS], g_cur[NBINS];
__device__ int    g_sorted[N_MAX];
__device__ int    g_is64;
__device__ double g_acc;

// ---------------- PTX helpers ----------------
__device__ __forceinline__ uint32_t smem_to_u32(const void* p) {
    uint32_t a;
    asm("{ .reg .u64 t; cvta.to.shared.u64 t, %1; cvt.u32.u64 %0, t; }" : "=r"(a) : "l"(p));
    return a;
}
__device__ __forceinline__ void cp16(uint32_t dst, const void* src) {
    asm volatile("cp.async.cg.shared.global [%0], [%1], 16;" :: "r"(dst), "l"(src) : "memory");
}
__device__ __forceinline__ void ldsm_x4(uint32_t* r, uint32_t addr) {
    asm volatile("ldmatrix.sync.aligned.m8n8.x4.shared.b16 {%0,%1,%2,%3}, [%4];"
                 : "=r"(r[0]), "=r"(r[1]), "=r"(r[2]), "=r"(r[3]) : "r"(addr));
}
__device__ __forceinline__ void mma16816(float* c, const uint32_t* a, const uint32_t* b) {
    asm volatile("mma.sync.aligned.m16n8k16.row.col.f32.bf16.bf16.f32 "
                 "{%0,%1,%2,%3}, {%4,%5,%6,%7}, {%8,%9}, {%0,%1,%2,%3};"
                 : "+f"(c[0]), "+f"(c[1]), "+f"(c[2]), "+f"(c[3])
                 : "r"(a[0]), "r"(a[1]), "r"(a[2]), "r"(a[3]), "r"(b[0]), "r"(b[1]));
}

// ---------------- K0: zero accumulators (fresh every replay) ----------------
__global__ void k_init() {
    int i = blockIdx.x * blockDim.x + threadIdx.x;
    if (i < N_MAX) { g_S1[i] = 0.f; g_S2[i] = 0.f; g_S3[i] = 0.f; }
    if (i < NBINS) { g_cnt[i] = 0; g_cur[i] = 0; }
    if (i == 0) g_acc = 0.0;
}

// ---------------- K0b: detect target dtype (int64 vs int32) ------------------
__global__ void k_detect(const int* __restrict__ w) {
    int nz = 0;
    for (int i = threadIdx.x; i < 64; i += 32)
        if (w[2 * i + 1] != 0) nz = 1;
    #pragma unroll
    for (int o = 16; o; o >>= 1) nz |= __shfl_xor_sync(0xffffffffu, nz, o);
    if (threadIdx.x == 0) g_is64 = nz ? 0 : 1;
}

// ---------------- K1: normalize; fp32 copies + padded bf16 operands ----------
__global__ void k_prep(const float* __restrict__ fs, const float* __restrict__ ft, int N) {
    int row = blockIdx.x;
    bool is_s = (row < N);
    int r = is_s ? row : row - N;
    int k = threadIdx.x;
    const float* src = is_s ? fs : ft;
    float v = src[r * D_FIX + k];
    float ss = v * v;
    #pragma unroll
    for (int o = 16; o; o >>= 1) ss += __shfl_xor_sync(0xffffffffu, ss, o);
    __shared__ float ws[4];
    if ((k & 31) == 0) ws[k >> 5] = ss;
    __syncthreads();
    float tot = ws[0] + ws[1] + ws[2] + ws[3];
    float nrm = fmaxf(sqrtf(tot), 1e-12f);
    float x = v * ((is_s ? NCE_INV_T : 1.0f) / nrm);
    (is_s ? g_f1 : g_f2)[r * D_FIX + k] = x;
    __nv_bfloat16* dst = is_s ? g_a16 : g_b16;
    dst[r * ROWE + k] = __float2bfloat16(x);
    if (k < ROWE - D_FIX) dst[r * ROWE + D_FIX + k] = __float2bfloat16(0.f); // pad
}

// ---------------- K2: class histogram + dtype-aware load ----------------
__global__ void k_count(const int* __restrict__ w, int N) {
    int i = blockIdx.x * blockDim.x + threadIdx.x;
    if (i < N) {
        int c = g_is64 ? w[2 * i] : w[i];
        if (c < 0 || c >= NBINS) c = 0;
        g_tgt[i] = c;
        atomicAdd(&g_cnt[c], 1);
    }
}

// ---------------- K3: exclusive scan over class counts (1 block) -------------
__global__ void k_scan() {
    __shared__ int s[NBINS];
    int t = threadIdx.x;
    s[t] = g_cnt[t];
    __syncthreads();
    for (int off = 1; off < NBINS; off <<= 1) {
        int v = (t >= off) ? s[t - off] : 0;
        __syncthreads();
        s[t] += v;
        __syncthreads();
    }
    g_off[t] = s[t] - g_cnt[t];
}

// ---------------- K5: bf16 mma.sync GEMM + fused exp power sums ---------------
// 128x128 tile/CTA, 8 warps (4m x 2n -> 32x64 warp tiles), K=128 resident.
// SMEM rows have +16B skew (272B stride) -> conflict-free ldmatrix.
__global__ __launch_bounds__(256, 2) void k_gemm() {
    extern __shared__ __align__(16) unsigned char smem[];
    uint32_t SAu = smem_to_u32(smem);
    uint32_t SBu = SAu + TILE_BYTES;
    int tid = threadIdx.x, lane = tid & 31, wid = tid >> 5;
    int wm = wid & 3, wn = wid >> 2;
    int row0 = blockIdx.y * TILE, col0 = blockIdx.x * TILE;

    // async copy both padded tiles (contiguous 34816 B each)
    const char* ga = (const char*)(g_a16 + (size_t)row0 * ROWE);
    const char* gb = (const char*)(g_b16 + (size_t)col0 * ROWE);
    for (int o = tid; o < TILE_BYTES / 16; o += 256) {
        cp16(SAu + o * 16, ga + o * 16);
        cp16(SBu + o * 16, gb + o * 16);
    }
    asm volatile("cp.async.commit_group;" ::: "memory");
    asm volatile("cp.async.wait_group 0;" ::: "memory");
    __syncthreads();

    // ldmatrix base addresses
    uint32_t a_base = SAu + (wm * 32 + (lane & 15)) * 272 + (((lane >> 4) & 1) << 3) * 2;
    uint32_t b_base = SBu + (wn * 64 + (((lane >> 4) & 1) << 3) + (lane & 7)) * 272
                          + (((lane >> 3) & 1) << 3) * 2;

    float c[2][8][4];
    #pragma unroll
    for (int mi = 0; mi < 2; mi++)
        #pragma unroll
        for (int ni = 0; ni < 8; ni++)
            #pragma unroll
            for (int j = 0; j < 4; j++) c[mi][ni][j] = 0.f;

    #pragma unroll
    for (int kb = 0; kb < 128; kb += 16) {
        uint32_t a[2][4], b[8][2];
        #pragma unroll
        for (int mi = 0; mi < 2; mi++)
            ldsm_x4(a[mi], a_base + mi * 16 * 272 + kb * 2);
        #pragma unroll
        for (int p = 0; p < 4; p++) {
            uint32_t r[4];
            ldsm_x4(r, b_base + p * 16 * 272 + kb * 2);
            b[2 * p][0] = r[0]; b[2 * p][1] = r[1];
            b[2 * p + 1][0] = r[2]; b[2 * p + 1][1] = r[3];
        }
        #pragma unroll
        for (int mi = 0; mi < 2; mi++)
            #pragma unroll
            for (int ni = 0; ni < 8; ni++)
                mma16816(c[mi][ni], a[mi], b[ni]);
    }

    // epilogue: e = exp(logit); per-row power sums (each thread owns 4 rows)
    float s1[4] = {0, 0, 0, 0}, s2[4] = {0, 0, 0, 0}, s3[4] = {0, 0, 0, 0};
    #pragma unroll
    for (int mi = 0; mi < 2; mi++)
        #pragma unroll
        for (int ni = 0; ni < 8; ni++)
            #pragma unroll
            for (int j = 0; j < 4; j++) {
                float e = __expf(c[mi][ni][j]);
                int idx = mi * 2 + (j >> 1);   // (mi, half)
                float e2 = e * e;
                s1[idx] += e; s2[idx] += e2; s3[idx] += e2 * e;
            }
    #pragma unroll
    for (int idx = 0; idx < 4; idx++) {
        #pragma unroll
        for (int o = 1; o <= 2; o <<= 1) {   // reduce over the 4 q-lanes of a row group
            s1[idx] += __shfl_xor_sync(0xffffffffu, s1[idx], o);
            s2[idx] += __shfl_xor_sync(0xffffffffu, s2[idx], o);
            s3[idx] += __shfl_xor_sync(0xffffffffu, s3[idx], o);
        }
    }
    if ((lane & 3) == 0) {
        int g = lane >> 2;
        #pragma unroll
        for (int idx = 0; idx < 4; idx++) {
            int mi = idx >> 1, half = idx & 1;
            int grow = row0 + wm * 32 + mi * 16 + half * 8 + g;
            atomicAdd(&g_S1[grow], s1[idx]);
            atomicAdd(&g_S2[grow], s2[idx]);
            atomicAdd(&g_S3[grow], s3[idx]);
        }
    }
}

// ---------------- K4: scatter row ids grouped by class ----------------
__global__ void k_scatter(int N) {
    int i = blockIdx.x * blockDim.x + threadIdx.x;
    if (i < N) {
        int c = g_tgt[i];
        int p = atomicAdd(&g_cur[c], 1);
        g_sorted[g_off[c] + p] = i;
    }
}

// ---------------- K6: exact pos-pair terms + assemble NCE row loss ------------
// -log(1-x) = x + x^2/2 + x^3/3 + O(x^4), ps <= ~0.005:
// sum over ALL j of series = 1 + S2/(2Z^2) + S3/(3Z^3); subtract exact pos part.
__global__ void k_pos(int N) {
    int i = blockIdx.x;
    int tid = threadIdx.x; // 128
    int c = g_tgt[i];
    int pcnt = g_cnt[c];
    int base = g_off[c];
    __shared__ __align__(16) float frow[D_FIX];
    frow[tid] = g_f1[i * D_FIX + tid];
    __syncthreads();
    float invZ = 1.0f / g_S1[i];
    float plog = 0.f, pser = 0.f;
    for (int t = tid; t < pcnt; t += 128) {
        int j = g_sorted[base + t];
        const float4* br = reinterpret_cast<const float4*>(g_f2 + j * D_FIX);
        const float4* ar = reinterpret_cast<const float4*>(frow);
        float dot = 0.f;
        #pragma unroll
        for (int q = 0; q < D_FIX / 4; q++) {
            float4 b4 = br[q], a4 = ar[q];
            dot += a4.x * b4.x + a4.y * b4.y + a4.z * b4.z + a4.w * b4.w;
        }
        float ps = __expf(dot) * invZ;
        plog -= __logf(ps + EPSV);
        pser += ps * (1.0f + ps * (0.5f + ps * (1.0f / 3.0f)));
    }
    #pragma unroll
    for (int o = 16; o; o >>= 1) {
        plog += __shfl_xor_sync(0xffffffffu, plog, o);
        pser += __shfl_xor_sync(0xffffffffu, pser, o);
    }
    __shared__ float r1[4], r2[4];
    if ((tid & 31) == 0) { r1[tid >> 5] = plog; r2[tid >> 5] = pser; }
    __syncthreads();
    if (tid == 0) {
        plog = r1[0] + r1[1] + r1[2] + r1[3];
        pser = r2[0] + r2[1] + r2[2] + r2[3];
        float s2 = g_S2[i] * invZ * invZ;
        float s3 = g_S3[i] * invZ * invZ * invZ;
        float tot = 1.0f + 0.5f * s2 + (1.0f / 3.0f) * s3;
        float negs = tot - pser;
        float row = plog / (float)pcnt + negs / (float)(N - pcnt);
        atomicAdd(&g_acc, (double)row / (double)N);
    }
}

// ---------------- K7: JSD rows (T=1) -----------------------------------------
__global__ void k_jsd(const float* __restrict__ ls, const float* __restrict__ lt,
                      int N, int C) {
    int i = blockIdx.x;
    int tid = threadIdx.x; // 256
    const float* s = ls + (size_t)i * C;
    const float* t = lt + (size_t)i * C;
    float es = 0.f, et = 0.f;
    for (int j = tid; j < C; j += 256) { es += __expf(s[j]); et += __expf(t[j]); }
    #pragma unroll
    for (int o = 16; o; o >>= 1) {
        es += __shfl_xor_sync(0xffffffffu, es, o);
        et += __shfl_xor_sync(0xffffffffu, et, o);
    }
    __shared__ float w1[8], w2[8];
    if ((tid & 31) == 0) { w1[tid >> 5] = es; w2[tid >> 5] = et; }
    __syncthreads();
    __shared__ float bs, bt;
    if (tid == 0) {
        float a = 0.f, b = 0.f;
        #pragma unroll
        for (int w = 0; w < 8; w++) { a += w1[w]; b += w2[w]; }
        bs = a; bt = b;
    }
    __syncthreads();
    float lzs = __logf(bs), lzt = __logf(bt);
    float invs = 1.0f / bs, invt = 1.0f / bt;
    float kl = 0.f;
    for (int j = tid; j < C; j += 256) {
        float a = s[j], b = t[j];
        float dl = (b - lzt) - (a - lzs);
        float pt = __expf(b) * invt;
        float ps = __expf(a) * invs;
        kl += (pt - ps) * dl;
    }
    #pragma unroll
    for (int o = 16; o; o >>= 1) kl += __shfl_xor_sync(0xffffffffu, kl, o);
    if ((tid & 31) == 0) w1[tid >> 5] = kl;
    __syncthreads();
    if (tid == 0) {
        float a = 0.f;
        #pragma unroll
        for (int w = 0; w < 8; w++) a += w1[w];
        atomicAdd(&g_acc, 0.5 * (double)a / (double)N);
    }
}

// ---------------- K8: write scalar output ----------------
__global__ void k_final(float* out) {
    if (threadIdx.x == 0) out[0] = (float)g_acc;
}

// ---------------- launcher ----------------
extern "C" void kernel_launch(void* const* d_in, const int* in_sizes, int n_in,
                              void* d_out, int out_size) {
    const float* fs = (const float*)d_in[0];
    const float* ft = (const float*)d_in[1];
    const float* ls = (const float*)d_in[2];
    const float* lt = (const float*)d_in[3];
    const int*   tg = (const int*)d_in[4];   // int32 or int64 words, detected on-device
    int N = in_sizes[4];
    int C = in_sizes[2] / N;
    int nt = N / TILE;

    cudaFuncSetAttribute(k_gemm, cudaFuncAttributeMaxDynamicSharedMemorySize, SMEM_GEMM);

    // launch order puts k_gemm at index 5 so ncu (-s 5 -c 1) profiles it
    k_init<<<(N_MAX + 255) / 256, 256>>>();                    // 0
    k_detect<<<1, 32>>>(tg);                                   // 1
    k_prep<<<2 * N, D_FIX>>>(fs, ft, N);                       // 2
    k_count<<<(N + 255) / 256, 256>>>(tg, N);                  // 3
    k_scan<<<1, NBINS>>>();                                    // 4
    dim3 grid(nt, nt);
    k_gemm<<<grid, 256, SMEM_GEMM>>>();                        // 5  <- profiled
    k_scatter<<<(N + 255) / 256, 256>>>(N);                    // 6
    k_pos<<<N, 128>>>(N);                                      // 7
    k_jsd<<<N, 256>>>(ls, lt, N, C);                           // 8
    k_final<<<1, 32>>>((float*)d_out);                         // 9
}